// round 1
// baseline (speedup 1.0000x reference)
#include <cuda_runtime.h>

#define N_NODES 50000
#define N_EDGES 800000
#define N_GRAPH 500
#define DIM     128
#define EDIM    7
#define LAYERS  5
#define NCLASS  10
#define BN_EPS  1e-5f

// ---------------- scratch (static device allocations; no cudaMalloc) ----------------
__device__ float g_x  [N_NODES * DIM];   // node features
__device__ float g_agg[N_NODES * DIM];   // x + sum(msg)   (initialized to x each layer)
__device__ float g_t1 [N_NODES * DIM];   // MLP intermediate
__device__ float g_pool[N_GRAPH * DIM];  // graph pooled sums
__device__ float g_cnt [N_GRAPH];        // per-graph node counts

// ---------------- init: x[n,:] = node_emb[0,:] ----------------
__global__ void k_init_x(const float* __restrict__ node_emb) {
    int i = blockIdx.x * blockDim.x + threadIdx.x;
    if (i < N_NODES * DIM) g_x[i] = node_emb[i & (DIM - 1)];
}

// ---------------- copy: agg = x (so h = x + sum msg falls out) ----------------
__global__ void k_copy_x_to_agg() {
    int i = blockIdx.x * blockDim.x + threadIdx.x;
    if (i < N_NODES * DIM / 4)
        reinterpret_cast<float4*>(g_agg)[i] = reinterpret_cast<const float4*>(g_x)[i];
}

// ---------------- edge phase: agg[dst] += relu(x[src] + edge_attr@W + b) ----------------
// one warp per edge; lane handles 4 consecutive dims (float4)
__global__ void k_edge(const float* __restrict__ edge_attr,
                       const int*   __restrict__ edge_index,
                       const float* __restrict__ eW,   // [EDIM, DIM]
                       const float* __restrict__ eb)   // [DIM]
{
    __shared__ float4 sW[EDIM * 32];
    __shared__ float4 sB[32];
    int tid = threadIdx.x;
    if (tid < EDIM * 32) sW[tid] = reinterpret_cast<const float4*>(eW)[tid];
    if (tid < 32)        sB[tid] = reinterpret_cast<const float4*>(eb)[tid];
    __syncthreads();

    int warp = tid >> 5, lane = tid & 31;
    int e = blockIdx.x * (blockDim.x >> 5) + warp;
    if (e >= N_EDGES) return;

    float v = (lane < EDIM) ? edge_attr[e * EDIM + lane] : 0.0f;
    float4 acc = sB[lane];
#pragma unroll
    for (int j = 0; j < EDIM; j++) {
        float a = __shfl_sync(0xffffffffu, v, j);
        float4 w = sW[j * 32 + lane];
        acc.x += a * w.x; acc.y += a * w.y; acc.z += a * w.z; acc.w += a * w.w;
    }

    int src = edge_index[e];
    int dst = edge_index[N_EDGES + e];
    float4 xv = reinterpret_cast<const float4*>(g_x)[src * 32 + lane];
    float4 m;
    m.x = fmaxf(xv.x + acc.x, 0.0f);
    m.y = fmaxf(xv.y + acc.y, 0.0f);
    m.z = fmaxf(xv.z + acc.z, 0.0f);
    m.w = fmaxf(xv.w + acc.w, 0.0f);

#if __CUDA_ARCH__ >= 900
    atomicAdd(reinterpret_cast<float4*>(g_agg) + dst * 32 + lane, m);
#else
    float* p = g_agg + dst * DIM + lane * 4;
    atomicAdd(p + 0, m.x); atomicAdd(p + 1, m.y);
    atomicAdd(p + 2, m.z); atomicAdd(p + 3, m.w);
#endif
}

// ---------------- fused Linear + BN + ReLU over all nodes ----------------
// out[n,o] = relu( (in[n,:]@W[:,o] + bias[o])*S[o] + T[o] )  with BN folded
// block = 128 threads (4 warps). Each warp handles one node per tile; lane
// computes output dims [4*lane .. 4*lane+3]. W lives in shared (64 KB),
// 1 LDS.128 per 4 FFMA.
#define MLP_SMEM ((128 * 32 + 4 * 32) * 16)
__global__ void __launch_bounds__(128) k_mlp(
    const float* __restrict__ in, float* __restrict__ out,
    const float* __restrict__ W,    const float* __restrict__ bias,
    const float* __restrict__ bng,  const float* __restrict__ bnb,
    const float* __restrict__ bnm,  const float* __restrict__ bnv)
{
    extern __shared__ float4 smem[];
    float4* sW = smem;             // [128][32] float4  (W[k][4l..4l+3])
    float4* sH = smem + 128 * 32;  // [4][32]  float4   (4 node rows)

    int tid = threadIdx.x;
    int warp = tid >> 5, lane = tid & 31;

    const float4* W4 = reinterpret_cast<const float4*>(W);
    for (int i = tid; i < 128 * 32; i += 128) sW[i] = W4[i];

    // fold BN for this lane's 4 outputs: y = acc*S + T
    int o = lane * 4;
    float4 gg = *reinterpret_cast<const float4*>(bng + o);
    float4 bb = *reinterpret_cast<const float4*>(bnb + o);
    float4 mm = *reinterpret_cast<const float4*>(bnm + o);
    float4 vv = *reinterpret_cast<const float4*>(bnv + o);
    float4 bi = *reinterpret_cast<const float4*>(bias + o);
    float4 S, T;
    S.x = gg.x * rsqrtf(vv.x + BN_EPS);
    S.y = gg.y * rsqrtf(vv.y + BN_EPS);
    S.z = gg.z * rsqrtf(vv.z + BN_EPS);
    S.w = gg.w * rsqrtf(vv.w + BN_EPS);
    T.x = (bi.x - mm.x) * S.x + bb.x;
    T.y = (bi.y - mm.y) * S.y + bb.y;
    T.z = (bi.z - mm.z) * S.z + bb.z;
    T.w = (bi.w - mm.w) * S.w + bb.w;
    __syncthreads();

    const int NT = (N_NODES + 3) / 4;
    for (int t = blockIdx.x; t < NT; t += gridDim.x) {
        int n = t * 4 + warp;
        if (n < N_NODES)
            sH[warp * 32 + lane] = reinterpret_cast<const float4*>(in)[n * 32 + lane];
        __syncthreads();
        if (n < N_NODES) {
            float4 acc = make_float4(0.f, 0.f, 0.f, 0.f);
#pragma unroll
            for (int k0 = 0; k0 < 128; k0 += 4) {
                float4 h4 = sH[warp * 32 + (k0 >> 2)];
                float hk[4] = {h4.x, h4.y, h4.z, h4.w};
#pragma unroll
                for (int kk = 0; kk < 4; kk++) {
                    float4 w4 = sW[(k0 + kk) * 32 + lane];
                    acc.x += hk[kk] * w4.x;
                    acc.y += hk[kk] * w4.y;
                    acc.z += hk[kk] * w4.z;
                    acc.w += hk[kk] * w4.w;
                }
            }
            float4 r;
            r.x = fmaxf(acc.x * S.x + T.x, 0.0f);
            r.y = fmaxf(acc.y * S.y + T.y, 0.0f);
            r.z = fmaxf(acc.z * S.z + T.z, 0.0f);
            r.w = fmaxf(acc.w * S.w + T.w, 0.0f);
            reinterpret_cast<float4*>(out)[n * 32 + lane] = r;
        }
        __syncthreads();
    }
}

// ---------------- pooling ----------------
__global__ void k_zero_pool() {
    int i = blockIdx.x * blockDim.x + threadIdx.x;
    if (i < N_GRAPH * DIM) g_pool[i] = 0.0f;
    if (i < N_GRAPH) g_cnt[i] = 0.0f;
}

__global__ void k_pool(const int* __restrict__ batch) {
    int gw = (blockIdx.x * blockDim.x + threadIdx.x) >> 5;
    int lane = threadIdx.x & 31;
    if (gw >= N_NODES) return;
    int c = batch[gw];
    float4 v = reinterpret_cast<const float4*>(g_x)[gw * 32 + lane];
#if __CUDA_ARCH__ >= 900
    atomicAdd(reinterpret_cast<float4*>(g_pool) + c * 32 + lane, v);
#else
    float* p = g_pool + c * DIM + lane * 4;
    atomicAdd(p + 0, v.x); atomicAdd(p + 1, v.y);
    atomicAdd(p + 2, v.z); atomicAdd(p + 3, v.w);
#endif
    if (lane == 0) atomicAdd(&g_cnt[c], 1.0f);
}

// ---------------- head: out = relu(g@W1+b1) @ W2 + b2 ----------------
__global__ void k_head(const float* __restrict__ W1, const float* __restrict__ b1,
                       const float* __restrict__ W2, const float* __restrict__ b2,
                       float* __restrict__ out)
{
    __shared__ float sg[DIM];
    __shared__ float sh[DIM];
    int c = blockIdx.x;
    int t = threadIdx.x;
    float cnt = fmaxf(g_cnt[c], 1.0f);
    sg[t] = g_pool[c * DIM + t] / cnt;
    __syncthreads();
    float acc = b1[t];
#pragma unroll 8
    for (int k = 0; k < DIM; k++) acc += sg[k] * W1[k * DIM + t];
    sh[t] = fmaxf(acc, 0.0f);
    __syncthreads();
    if (t < NCLASS) {
        float o = b2[t];
#pragma unroll 8
        for (int k = 0; k < DIM; k++) o += sh[k] * W2[k * NCLASS + t];
        out[c * NCLASS + t] = o;
    }
}

// ---------------- launch ----------------
extern "C" void kernel_launch(void* const* d_in, const int* in_sizes, int n_in,
                              void* d_out, int out_size)
{
    const float* edge_attr = (const float*)d_in[0];
    const int*   edge_index= (const int*)  d_in[1];
    const int*   batch     = (const int*)  d_in[2];
    const float* node_emb  = (const float*)d_in[3];
    const float* edge_W    = (const float*)d_in[4];
    const float* edge_b    = (const float*)d_in[5];
    const float* mlp_W1    = (const float*)d_in[6];
    const float* mlp_b1    = (const float*)d_in[7];
    const float* bn1_g     = (const float*)d_in[8];
    const float* bn1_b     = (const float*)d_in[9];
    const float* bn1_m     = (const float*)d_in[10];
    const float* bn1_v     = (const float*)d_in[11];
    const float* mlp_W2    = (const float*)d_in[12];
    const float* mlp_b2    = (const float*)d_in[13];
    const float* bn2_g     = (const float*)d_in[14];
    const float* bn2_b     = (const float*)d_in[15];
    const float* bn2_m     = (const float*)d_in[16];
    const float* bn2_v     = (const float*)d_in[17];
    const float* head_W1   = (const float*)d_in[18];
    const float* head_b1   = (const float*)d_in[19];
    const float* head_W2   = (const float*)d_in[20];
    const float* head_b2   = (const float*)d_in[21];
    float* out = (float*)d_out;

    cudaFuncSetAttribute(k_mlp, cudaFuncAttributeMaxDynamicSharedMemorySize, MLP_SMEM);

    float *px, *pagg, *pt1;
    cudaGetSymbolAddress((void**)&px,   g_x);
    cudaGetSymbolAddress((void**)&pagg, g_agg);
    cudaGetSymbolAddress((void**)&pt1,  g_t1);

    k_init_x<<<(N_NODES * DIM + 255) / 256, 256>>>(node_emb);

    const int MLP_GRID = 444;  // 3 blocks/SM (64KB smem each) x 148 SMs
    for (int l = 0; l < LAYERS; l++) {
        k_copy_x_to_agg<<<(N_NODES * DIM / 4 + 255) / 256, 256>>>();
        k_edge<<<N_EDGES / 8, 256>>>(edge_attr, edge_index,
                                     edge_W + l * EDIM * DIM, edge_b + l * DIM);
        k_mlp<<<MLP_GRID, 128, MLP_SMEM>>>(
            pagg, pt1,
            mlp_W1 + l * DIM * DIM, mlp_b1 + l * DIM,
            bn1_g + l * DIM, bn1_b + l * DIM, bn1_m + l * DIM, bn1_v + l * DIM);
        k_mlp<<<MLP_GRID, 128, MLP_SMEM>>>(
            pt1, px,
            mlp_W2 + l * DIM * DIM, mlp_b2 + l * DIM,
            bn2_g + l * DIM, bn2_b + l * DIM, bn2_m + l * DIM, bn2_v + l * DIM);
    }

    k_zero_pool<<<(N_GRAPH * DIM + 255) / 256, 256>>>();
    k_pool<<<(N_NODES * 32 + 255) / 256, 256>>>(batch);
    k_head<<<N_GRAPH, DIM>>>(head_W1, head_b1, head_W2, head_b2, out);
}

// round 3
// speedup vs baseline: 1.9093x; 1.9093x over previous
#include <cuda_runtime.h>

#define N_NODES 50000
#define N_EDGES 800000
#define N_GRAPH 500
#define DIM     128
#define EDIM    7
#define LAYERS  5
#define NCLASS  10
#define BN_EPS  1e-5f

// ---------------- scratch ----------------
__device__ float g_x  [N_NODES * DIM];
__device__ float g_agg[N_NODES * DIM];
__device__ float g_t1 [N_NODES * DIM];
__device__ float g_pool[N_GRAPH * DIM];
__device__ float g_gcnt[N_GRAPH];

// CSR scratch
__device__ int g_deg [N_NODES];
__device__ int g_off [N_NODES + 1];
__device__ int g_bsum[256];
__device__ int g_fill[N_NODES];
__device__ int g_eid [N_EDGES];
__device__ int g_esrc[N_EDGES];

// ---------------- init ----------------
__global__ void k_init_x(const float* __restrict__ node_emb) {
    int i = blockIdx.x * blockDim.x + threadIdx.x;
    if (i < N_NODES * DIM) g_x[i] = node_emb[i & (DIM - 1)];
}

// ---------------- CSR build ----------------
__global__ void k_zero_deg() {
    int i = blockIdx.x * blockDim.x + threadIdx.x;
    if (i < N_NODES) g_deg[i] = 0;
}
__global__ void k_hist(const int* __restrict__ ei) {
    int e = blockIdx.x * blockDim.x + threadIdx.x;
    if (e < N_EDGES) atomicAdd(&g_deg[ei[N_EDGES + e]], 1);
}
#define SCAN_BLOCKS ((N_NODES + 255) / 256)   // 196
__global__ void k_blocksum() {
    __shared__ int s[256];
    int i = blockIdx.x * 256 + threadIdx.x;
    s[threadIdx.x] = (i < N_NODES) ? g_deg[i] : 0;
    __syncthreads();
    for (int d = 128; d > 0; d >>= 1) {
        if (threadIdx.x < d) s[threadIdx.x] += s[threadIdx.x + d];
        __syncthreads();
    }
    if (threadIdx.x == 0) g_bsum[blockIdx.x] = s[0];
}
__global__ void k_scan_bsum() {  // 1 block, 256 threads
    __shared__ int s[256];
    int v = (threadIdx.x < SCAN_BLOCKS) ? g_bsum[threadIdx.x] : 0;
    s[threadIdx.x] = v;
    __syncthreads();
    for (int d = 1; d < 256; d <<= 1) {
        int t = (threadIdx.x >= d) ? s[threadIdx.x - d] : 0;
        __syncthreads();
        s[threadIdx.x] += t;
        __syncthreads();
    }
    if (threadIdx.x < SCAN_BLOCKS) g_bsum[threadIdx.x] = s[threadIdx.x] - v;  // exclusive
}
__global__ void k_scan_final() {
    __shared__ int s[256];
    int i = blockIdx.x * 256 + threadIdx.x;
    int v = (i < N_NODES) ? g_deg[i] : 0;
    s[threadIdx.x] = v;
    __syncthreads();
    for (int d = 1; d < 256; d <<= 1) {
        int t = (threadIdx.x >= d) ? s[threadIdx.x - d] : 0;
        __syncthreads();
        s[threadIdx.x] += t;
        __syncthreads();
    }
    int excl = s[threadIdx.x] - v + g_bsum[blockIdx.x];
    if (i < N_NODES) { g_off[i] = excl; g_fill[i] = excl; }
    if (i == N_NODES - 1) g_off[N_NODES] = excl + v;
}
__global__ void k_scatter(const int* __restrict__ ei) {
    int e = blockIdx.x * blockDim.x + threadIdx.x;
    if (e < N_EDGES) {
        int dst = ei[N_EDGES + e];
        int p = atomicAdd(&g_fill[dst], 1);
        g_eid[p] = e;
        g_esrc[p] = ei[e];
    }
}

// ---------------- edge aggregation via CSR: g_agg[dst] = x[dst] + sum relu(x[src] + attr@W + b)
// one warp per dst node, lane owns 4 dims (float4), no atomics
__global__ void __launch_bounds__(256) k_edge_csr(
    const float* __restrict__ edge_attr,
    const float* __restrict__ eW,   // [EDIM, DIM]
    const float* __restrict__ eb)   // [DIM]
{
    __shared__ float4 sW[EDIM * 32];
    __shared__ float4 sB[32];
    int tid = threadIdx.x;
    if (tid < EDIM * 32) sW[tid] = reinterpret_cast<const float4*>(eW)[tid];
    if (tid < 32)        sB[tid] = reinterpret_cast<const float4*>(eb)[tid];
    __syncthreads();

    int warp = tid >> 5, lane = tid & 31;
    int dst = blockIdx.x * 8 + warp;
    if (dst >= N_NODES) return;

    float4 acc = reinterpret_cast<const float4*>(g_x)[dst * 32 + lane];  // seed with x -> h = x + agg
    float4 b = sB[lane];
    int beg = g_off[dst], end = g_off[dst + 1];

#pragma unroll 2
    for (int j = beg; j < end; j++) {
        int eid = g_eid[j];
        int src = g_esrc[j];
        float v = (lane < EDIM) ? edge_attr[eid * EDIM + lane] : 0.0f;
        float4 e = b;
#pragma unroll
        for (int q = 0; q < EDIM; q++) {
            float a = __shfl_sync(0xffffffffu, v, q);
            float4 w = sW[q * 32 + lane];
            e.x += a * w.x; e.y += a * w.y; e.z += a * w.z; e.w += a * w.w;
        }
        float4 xv = reinterpret_cast<const float4*>(g_x)[src * 32 + lane];
        acc.x += fmaxf(xv.x + e.x, 0.0f);
        acc.y += fmaxf(xv.y + e.y, 0.0f);
        acc.z += fmaxf(xv.z + e.z, 0.0f);
        acc.w += fmaxf(xv.w + e.w, 0.0f);
    }
    reinterpret_cast<float4*>(g_agg)[dst * 32 + lane] = acc;
}

// ---------------- fused Linear+BN+ReLU, register-tiled: 8 nodes per warp ----------------
// block 256 thr (8 warps) -> 64-node tile. sW 64KB + sH 32KB smem.
#define MLP_SMEM2 ((4096 + 2048) * 16)
__global__ void __launch_bounds__(256) k_mlp2(
    const float* __restrict__ in, float* __restrict__ out,
    const float* __restrict__ W,    const float* __restrict__ bias,
    const float* __restrict__ bng,  const float* __restrict__ bnb,
    const float* __restrict__ bnm,  const float* __restrict__ bnv)
{
    extern __shared__ float4 sm[];
    float4* sW = sm;           // [128][32] float4
    float4* sH = sm + 4096;    // [64][32]  float4

    int tid = threadIdx.x;
    int warp = tid >> 5, lane = tid & 31;

    const float4* W4 = reinterpret_cast<const float4*>(W);
#pragma unroll
    for (int i = 0; i < 16; i++) sW[tid + i * 256] = W4[tid + i * 256];

    // fold BN into scale/shift for this lane's 4 outputs
    int o = lane * 4;
    float4 gg = *reinterpret_cast<const float4*>(bng + o);
    float4 bb = *reinterpret_cast<const float4*>(bnb + o);
    float4 mm = *reinterpret_cast<const float4*>(bnm + o);
    float4 vv = *reinterpret_cast<const float4*>(bnv + o);
    float4 bi = *reinterpret_cast<const float4*>(bias + o);
    float4 S, T;
    S.x = gg.x * rsqrtf(vv.x + BN_EPS);
    S.y = gg.y * rsqrtf(vv.y + BN_EPS);
    S.z = gg.z * rsqrtf(vv.z + BN_EPS);
    S.w = gg.w * rsqrtf(vv.w + BN_EPS);
    T.x = (bi.x - mm.x) * S.x + bb.x;
    T.y = (bi.y - mm.y) * S.y + bb.y;
    T.z = (bi.z - mm.z) * S.z + bb.z;
    T.w = (bi.w - mm.w) * S.w + bb.w;

    int base = blockIdx.x * 64;
#pragma unroll
    for (int i = 0; i < 8; i++) {
        int idx = tid + i * 256;
        int row = base + (idx >> 5);
        sH[idx] = (row < N_NODES)
                    ? reinterpret_cast<const float4*>(in)[row * 32 + (idx & 31)]
                    : make_float4(0.f, 0.f, 0.f, 0.f);
    }
    __syncthreads();

    float4 acc[8];
#pragma unroll
    for (int i = 0; i < 8; i++) acc[i] = make_float4(0.f, 0.f, 0.f, 0.f);

#pragma unroll 4
    for (int k0 = 0; k0 < 128; k0 += 4) {
        float4 w0 = sW[(k0 + 0) * 32 + lane];
        float4 w1 = sW[(k0 + 1) * 32 + lane];
        float4 w2 = sW[(k0 + 2) * 32 + lane];
        float4 w3 = sW[(k0 + 3) * 32 + lane];
#pragma unroll
        for (int i = 0; i < 8; i++) {
            float4 h = sH[(warp * 8 + i) * 32 + (k0 >> 2)];
            acc[i].x = fmaf(h.x, w0.x, fmaf(h.y, w1.x, fmaf(h.z, w2.x, fmaf(h.w, w3.x, acc[i].x))));
            acc[i].y = fmaf(h.x, w0.y, fmaf(h.y, w1.y, fmaf(h.z, w2.y, fmaf(h.w, w3.y, acc[i].y))));
            acc[i].z = fmaf(h.x, w0.z, fmaf(h.y, w1.z, fmaf(h.z, w2.z, fmaf(h.w, w3.z, acc[i].z))));
            acc[i].w = fmaf(h.x, w0.w, fmaf(h.y, w1.w, fmaf(h.z, w2.w, fmaf(h.w, w3.w, acc[i].w))));
        }
    }

#pragma unroll
    for (int i = 0; i < 8; i++) {
        int row = base + warp * 8 + i;
        if (row < N_NODES) {
            float4 r;
            r.x = fmaxf(acc[i].x * S.x + T.x, 0.0f);
            r.y = fmaxf(acc[i].y * S.y + T.y, 0.0f);
            r.z = fmaxf(acc[i].z * S.z + T.z, 0.0f);
            r.w = fmaxf(acc[i].w * S.w + T.w, 0.0f);
            reinterpret_cast<float4*>(out)[row * 32 + lane] = r;
        }
    }
}

// ---------------- pooling ----------------
__global__ void k_zero_pool() {
    int i = blockIdx.x * blockDim.x + threadIdx.x;
    if (i < N_GRAPH * DIM) g_pool[i] = 0.0f;
    if (i < N_GRAPH) g_gcnt[i] = 0.0f;
}
__global__ void k_pool(const int* __restrict__ batch) {
    int gw = (blockIdx.x * blockDim.x + threadIdx.x) >> 5;
    int lane = threadIdx.x & 31;
    if (gw >= N_NODES) return;
    int c = batch[gw];
    float4 v = reinterpret_cast<const float4*>(g_x)[gw * 32 + lane];
    atomicAdd(reinterpret_cast<float4*>(g_pool) + c * 32 + lane, v);
    if (lane == 0) atomicAdd(&g_gcnt[c], 1.0f);
}

// ---------------- head ----------------
__global__ void k_head(const float* __restrict__ W1, const float* __restrict__ b1,
                       const float* __restrict__ W2, const float* __restrict__ b2,
                       float* __restrict__ out)
{
    __shared__ float sg[DIM];
    __shared__ float sh[DIM];
    int c = blockIdx.x;
    int t = threadIdx.x;
    float cnt = fmaxf(g_gcnt[c], 1.0f);
    sg[t] = g_pool[c * DIM + t] / cnt;
    __syncthreads();
    float acc = b1[t];
#pragma unroll 8
    for (int k = 0; k < DIM; k++) acc += sg[k] * W1[k * DIM + t];
    sh[t] = fmaxf(acc, 0.0f);
    __syncthreads();
    if (t < NCLASS) {
        float o2 = b2[t];
#pragma unroll 8
        for (int k = 0; k < DIM; k++) o2 += sh[k] * W2[k * NCLASS + t];
        out[c * NCLASS + t] = o2;
    }
}

// ---------------- launch ----------------
extern "C" void kernel_launch(void* const* d_in, const int* in_sizes, int n_in,
                              void* d_out, int out_size)
{
    const float* edge_attr = (const float*)d_in[0];
    const int*   edge_index= (const int*)  d_in[1];
    const int*   batch     = (const int*)  d_in[2];
    const float* node_emb  = (const float*)d_in[3];
    const float* edge_W    = (const float*)d_in[4];
    const float* edge_b    = (const float*)d_in[5];
    const float* mlp_W1    = (const float*)d_in[6];
    const float* mlp_b1    = (const float*)d_in[7];
    const float* bn1_g     = (const float*)d_in[8];
    const float* bn1_b     = (const float*)d_in[9];
    const float* bn1_m     = (const float*)d_in[10];
    const float* bn1_v     = (const float*)d_in[11];
    const float* mlp_W2    = (const float*)d_in[12];
    const float* mlp_b2    = (const float*)d_in[13];
    const float* bn2_g     = (const float*)d_in[14];
    const float* bn2_b     = (const float*)d_in[15];
    const float* bn2_m     = (const float*)d_in[16];
    const float* bn2_v     = (const float*)d_in[17];
    const float* head_W1   = (const float*)d_in[18];
    const float* head_b1   = (const float*)d_in[19];
    const float* head_W2   = (const float*)d_in[20];
    const float* head_b2   = (const float*)d_in[21];
    float* out = (float*)d_out;

    cudaFuncSetAttribute(k_mlp2, cudaFuncAttributeMaxDynamicSharedMemorySize, MLP_SMEM2);

    float *px, *pagg, *pt1;
    cudaGetSymbolAddress((void**)&px,   g_x);
    cudaGetSymbolAddress((void**)&pagg, g_agg);
    cudaGetSymbolAddress((void**)&pt1,  g_t1);

    // init node features + CSR build (per replay, deterministic)
    k_init_x<<<(N_NODES * DIM + 255) / 256, 256>>>(node_emb);
    k_zero_deg<<<SCAN_BLOCKS, 256>>>();
    k_hist<<<(N_EDGES + 255) / 256, 256>>>(edge_index);
    k_blocksum<<<SCAN_BLOCKS, 256>>>();
    k_scan_bsum<<<1, 256>>>();
    k_scan_final<<<SCAN_BLOCKS, 256>>>();
    k_scatter<<<(N_EDGES + 255) / 256, 256>>>(edge_index);

    const int MLP_GRID = (N_NODES + 63) / 64;  // 782
    for (int l = 0; l < LAYERS; l++) {
        k_edge_csr<<<(N_NODES + 7) / 8, 256>>>(edge_attr,
                                               edge_W + l * EDIM * DIM,
                                               edge_b + l * DIM);
        k_mlp2<<<MLP_GRID, 256, MLP_SMEM2>>>(
            pagg, pt1,
            mlp_W1 + l * DIM * DIM, mlp_b1 + l * DIM,
            bn1_g + l * DIM, bn1_b + l * DIM, bn1_m + l * DIM, bn1_v + l * DIM);
        k_mlp2<<<MLP_GRID, 256, MLP_SMEM2>>>(
            pt1, px,
            mlp_W2 + l * DIM * DIM, mlp_b2 + l * DIM,
            bn2_g + l * DIM, bn2_b + l * DIM, bn2_m + l * DIM, bn2_v + l * DIM);
    }

    k_zero_pool<<<(N_GRAPH * DIM + 255) / 256, 256>>>();
    k_pool<<<(N_NODES * 32 + 255) / 256, 256>>>(batch);
    k_head<<<N_GRAPH, DIM>>>(head_W1, head_b1, head_W2, head_b2, out);
}

// round 8
// speedup vs baseline: 2.1658x; 1.1344x over previous
#include <cuda_runtime.h>
#include <cuda_bf16.h>
#include <cstdint>

#define N_NODES 50000
#define N_EDGES 800000
#define N_GRAPH 500
#define DIM     128
#define EDIM    7
#define LAYERS  5
#define NCLASS  10
#define BN_EPS  1e-5f

// ---------------- scratch ----------------
__device__ float g_x  [N_NODES * DIM];
__device__ float g_agg[N_NODES * DIM];
__device__ float g_t1 [N_NODES * DIM];
__device__ float g_pool[N_GRAPH * DIM];
__device__ float g_gcnt[N_GRAPH];

// CSR scratch
__device__ int   g_deg [N_NODES];
__device__ int   g_off [N_NODES + 1];
__device__ int   g_bsum[256];
__device__ int   g_fill[N_NODES];
__device__ int   g_esrc[N_EDGES];
__device__ float g_eattr[(size_t)N_EDGES * 8];   // attr pre-gathered into CSR order (padded to 8)

// transposed + bf16-split weight images, plain row-major [o][k] (10 mats: l*2 + {W1,W2})
__device__ __nv_bfloat16 g_Wh[10 * 16384];
__device__ __nv_bfloat16 g_Wl[10 * 16384];

// ================= helpers =================
__device__ __forceinline__ uint32_t smem_u32(const void* p) {
    uint32_t a;
    asm("{ .reg .u64 t; cvta.to.shared.u64 t, %1; cvt.u32.u64 %0, t; }" : "=r"(a) : "l"(p));
    return a;
}
__device__ __forceinline__ void ldm4(uint32_t* r, uint32_t addr) {
    asm volatile("ldmatrix.sync.aligned.m8n8.x4.shared.b16 {%0,%1,%2,%3}, [%4];"
                 : "=r"(r[0]), "=r"(r[1]), "=r"(r[2]), "=r"(r[3]) : "r"(addr));
}
__device__ __forceinline__ void mma_bf16(float* c, const uint32_t* a, uint32_t b0, uint32_t b1) {
    asm volatile("mma.sync.aligned.m16n8k16.row.col.f32.bf16.bf16.f32 "
                 "{%0,%1,%2,%3}, {%4,%5,%6,%7}, {%8,%9}, {%0,%1,%2,%3};"
                 : "+f"(c[0]), "+f"(c[1]), "+f"(c[2]), "+f"(c[3])
                 : "r"(a[0]), "r"(a[1]), "r"(a[2]), "r"(a[3]), "r"(b0), "r"(b1));
}

// ---------------- init ----------------
__global__ void k_init_x(const float* __restrict__ node_emb) {
    int i = blockIdx.x * blockDim.x + threadIdx.x;
    if (i < N_NODES * DIM) g_x[i] = node_emb[i & (DIM - 1)];
}

// ---------------- weight prep: transpose + bf16 hi/lo split (plain [o][k] layout) ----------------
__global__ void k_prep_w(const float* __restrict__ W1, const float* __restrict__ W2) {
    int idx = blockIdx.x * blockDim.x + threadIdx.x;
    if (idx >= 10 * 16384) return;
    int mat = idx >> 14;
    int r = idx & 16383;
    int o = r >> 7, k = r & 127;
    int l = mat >> 1;
    const float* W = (mat & 1) ? (W2 + l * 16384) : (W1 + l * 16384);
    float x = W[k * 128 + o];
    __nv_bfloat16 h = __float2bfloat16(x);
    __nv_bfloat16 lo = __float2bfloat16(x - __bfloat162float(h));
    g_Wh[mat * 16384 + o * 128 + k] = h;
    g_Wl[mat * 16384 + o * 128 + k] = lo;
}

// ---------------- CSR build ----------------
__global__ void k_zero_deg() {
    int i = blockIdx.x * blockDim.x + threadIdx.x;
    if (i < N_NODES) g_deg[i] = 0;
}
__global__ void k_hist(const int* __restrict__ ei) {
    int e = blockIdx.x * blockDim.x + threadIdx.x;
    if (e < N_EDGES) atomicAdd(&g_deg[ei[N_EDGES + e]], 1);
}
#define SCAN_BLOCKS ((N_NODES + 255) / 256)   // 196
__global__ void k_blocksum() {
    __shared__ int s[256];
    int i = blockIdx.x * 256 + threadIdx.x;
    s[threadIdx.x] = (i < N_NODES) ? g_deg[i] : 0;
    __syncthreads();
    for (int d = 128; d > 0; d >>= 1) {
        if (threadIdx.x < d) s[threadIdx.x] += s[threadIdx.x + d];
        __syncthreads();
    }
    if (threadIdx.x == 0) g_bsum[blockIdx.x] = s[0];
}
__global__ void k_scan_bsum() {
    __shared__ int s[256];
    int v = (threadIdx.x < SCAN_BLOCKS) ? g_bsum[threadIdx.x] : 0;
    s[threadIdx.x] = v;
    __syncthreads();
    for (int d = 1; d < 256; d <<= 1) {
        int t = (threadIdx.x >= d) ? s[threadIdx.x - d] : 0;
        __syncthreads();
        s[threadIdx.x] += t;
        __syncthreads();
    }
    if (threadIdx.x < SCAN_BLOCKS) g_bsum[threadIdx.x] = s[threadIdx.x] - v;
}
__global__ void k_scan_final() {
    __shared__ int s[256];
    int i = blockIdx.x * 256 + threadIdx.x;
    int v = (i < N_NODES) ? g_deg[i] : 0;
    s[threadIdx.x] = v;
    __syncthreads();
    for (int d = 1; d < 256; d <<= 1) {
        int t = (threadIdx.x >= d) ? s[threadIdx.x - d] : 0;
        __syncthreads();
        s[threadIdx.x] += t;
        __syncthreads();
    }
    int excl = s[threadIdx.x] - v + g_bsum[blockIdx.x];
    if (i < N_NODES) { g_off[i] = excl; g_fill[i] = excl; }
    if (i == N_NODES - 1) g_off[N_NODES] = excl + v;
}
__global__ void k_scatter(const int* __restrict__ ei, const float* __restrict__ attr) {
    int e = blockIdx.x * blockDim.x + threadIdx.x;
    if (e < N_EDGES) {
        int dst = ei[N_EDGES + e];
        int p = atomicAdd(&g_fill[dst], 1);
        g_esrc[p] = ei[e];
        float* d = g_eattr + (size_t)p * 8;
#pragma unroll
        for (int i = 0; i < 7; i++) d[i] = attr[e * 7 + i];
    }
}

// ---------------- edge aggregation via CSR (attr streamed in CSR order) ----------------
__global__ void __launch_bounds__(256) k_edge_csr(
    const float* __restrict__ eW, const float* __restrict__ eb)
{
    __shared__ float4 sW[EDIM * 32];
    __shared__ float4 sB[32];
    int tid = threadIdx.x;
    if (tid < EDIM * 32) sW[tid] = reinterpret_cast<const float4*>(eW)[tid];
    if (tid < 32)        sB[tid] = reinterpret_cast<const float4*>(eb)[tid];
    __syncthreads();

    int warp = tid >> 5, lane = tid & 31;
    int dst = blockIdx.x * 8 + warp;
    if (dst >= N_NODES) return;

    float4 acc = reinterpret_cast<const float4*>(g_x)[dst * 32 + lane];
    float4 b = sB[lane];
    int beg = g_off[dst], end = g_off[dst + 1];

#pragma unroll 2
    for (int j = beg; j < end; j++) {
        int src = g_esrc[j];
        float v = (lane < EDIM) ? g_eattr[(size_t)j * 8 + lane] : 0.0f;
        float4 e = b;
#pragma unroll
        for (int q = 0; q < EDIM; q++) {
            float a = __shfl_sync(0xffffffffu, v, q);
            float4 w = sW[q * 32 + lane];
            e.x += a * w.x; e.y += a * w.y; e.z += a * w.z; e.w += a * w.w;
        }
        float4 xv = reinterpret_cast<const float4*>(g_x)[src * 32 + lane];
        acc.x += fmaxf(xv.x + e.x, 0.0f);
        acc.y += fmaxf(xv.y + e.y, 0.0f);
        acc.z += fmaxf(xv.z + e.z, 0.0f);
        acc.w += fmaxf(xv.w + e.w, 0.0f);
    }
    reinterpret_cast<float4*>(g_agg)[dst * 32 + lane] = acc;
}

// ---------------- MLP: mma.sync bf16x3 split GEMM, fused BN+ReLU ----------------
// block 256 thr = 8 warps; tile 128 rows x 128 cols; warp = 32 rows x 64 cols.
// smem: W hi/lo + A hi/lo in [128][136] bf16 padded layout (conflict-free ldmatrix), S/T.
#define PAD 136
#define SM_W_BYTES (128 * PAD * 2)
#define MLP_SMEM (4 * SM_W_BYTES + 1024)

__global__ void __launch_bounds__(256, 1) k_mlp_mma(
    const float* __restrict__ in, float* __restrict__ out,
    const __nv_bfloat16* __restrict__ Wh, const __nv_bfloat16* __restrict__ Wl,
    const float* __restrict__ bias,
    const float* __restrict__ bng, const float* __restrict__ bnb,
    const float* __restrict__ bnm, const float* __restrict__ bnv)
{
    extern __shared__ char sm[];
    __nv_bfloat16* sWh = reinterpret_cast<__nv_bfloat16*>(sm);
    __nv_bfloat16* sWl = sWh + 128 * PAD;
    __nv_bfloat16* sAh = sWl + 128 * PAD;
    __nv_bfloat16* sAl = sAh + 128 * PAD;
    float* Sarr = reinterpret_cast<float*>(sAl + 128 * PAD);
    float* Tarr = Sarr + 128;

    int tid = threadIdx.x, wid = tid >> 5, lane = tid & 31;

    // load W images into padded smem (8 bf16 per uint4)
    for (int i = tid; i < 2048; i += 256) {
        int o = i >> 4, kc = (i & 15) * 8;
        *reinterpret_cast<uint4*>(sWh + o * PAD + kc) = reinterpret_cast<const uint4*>(Wh)[i];
        *reinterpret_cast<uint4*>(sWl + o * PAD + kc) = reinterpret_cast<const uint4*>(Wl)[i];
    }
    if (tid < 128) {
        float S = bng[tid] * rsqrtf(bnv[tid] + BN_EPS);
        Sarr[tid] = S;
        Tarr[tid] = (bias[tid] - bnm[tid]) * S + bnb[tid];
    }

    // warp coords: wm in 0..3 (row group of 32), wn in 0..1 (col group of 64)
    int wm = wid & 3, wn = wid >> 1 >> 1;  // wn = wid >> 2
    wn = wid >> 2;

    // ldmatrix element addresses
    uint32_t aOff = ((uint32_t)(wm * 32 + (lane & 15)) * PAD + (lane >> 4) * 8) * 2;
    uint32_t bOff = ((uint32_t)(wn * 64 + (lane & 7) + ((lane >> 3) & 1) * 8) * PAD + (lane >> 4) * 8) * 2;
    uint32_t adrAh = smem_u32(sAh) + aOff;
    uint32_t adrAl = smem_u32(sAl) + aOff;
    uint32_t adrBh = smem_u32(sWh) + bOff;
    uint32_t adrBl = smem_u32(sWl) + bOff;

    const int NTILES = (N_NODES + 127) / 128;   // 391
    const int m = tid >> 1;
    const int kh = (tid & 1) * 64;

    for (int t = blockIdx.x; t < NTILES; t += gridDim.x) {
        int base = t * 128;
        __syncthreads();   // all warps done with previous tile's sA

        // ---- A: fp32 -> bf16 hi/lo split into padded smem ----
        {
            int row = base + m;
            const float* inrow = in + (size_t)row * 128 + kh;
#pragma unroll
            for (int j = 0; j < 8; j++) {
                float f[8];
                if (row < N_NODES) {
                    float4 a = *reinterpret_cast<const float4*>(inrow + j * 8);
                    float4 bq = *reinterpret_cast<const float4*>(inrow + j * 8 + 4);
                    f[0] = a.x; f[1] = a.y; f[2] = a.z; f[3] = a.w;
                    f[4] = bq.x; f[5] = bq.y; f[6] = bq.z; f[7] = bq.w;
                } else {
#pragma unroll
                    for (int p = 0; p < 8; p++) f[p] = 0.0f;
                }
                uint32_t hi[4], lo[4];
#pragma unroll
                for (int p = 0; p < 4; p++) {
                    float x0 = f[2 * p], x1 = f[2 * p + 1];
                    __nv_bfloat16 h0 = __float2bfloat16(x0);
                    __nv_bfloat16 h1 = __float2bfloat16(x1);
                    __nv_bfloat162 hp; hp.x = h0; hp.y = h1;
                    __nv_bfloat162 lp;
                    lp.x = __float2bfloat16(x0 - __bfloat162float(h0));
                    lp.y = __float2bfloat16(x1 - __bfloat162float(h1));
                    hi[p] = *reinterpret_cast<uint32_t*>(&hp);
                    lo[p] = *reinterpret_cast<uint32_t*>(&lp);
                }
                int off = m * PAD + kh + j * 8;
                *reinterpret_cast<uint4*>(sAh + off) = make_uint4(hi[0], hi[1], hi[2], hi[3]);
                *reinterpret_cast<uint4*>(sAl + off) = make_uint4(lo[0], lo[1], lo[2], lo[3]);
            }
        }
        __syncthreads();

        // ---- GEMM: acc = Ah*Bh + Al*Bh + Ah*Bl ----
        float acc[2][8][4];
#pragma unroll
        for (int mt = 0; mt < 2; mt++)
#pragma unroll
            for (int nt = 0; nt < 8; nt++)
#pragma unroll
                for (int q = 0; q < 4; q++) acc[mt][nt][q] = 0.0f;

#pragma unroll
        for (int ks = 0; ks < 8; ks++) {
            uint32_t k2 = ks * 32;   // byte offset of k0=ks*16
            uint32_t ah[2][4], al[2][4], bh[4][4], bl[4][4];
            ldm4(ah[0], adrAh + k2);
            ldm4(ah[1], adrAh + 16 * PAD * 2 + k2);
            ldm4(al[0], adrAl + k2);
            ldm4(al[1], adrAl + 16 * PAD * 2 + k2);
#pragma unroll
            for (int p = 0; p < 4; p++) {
                ldm4(bh[p], adrBh + p * 16 * PAD * 2 + k2);
                ldm4(bl[p], adrBl + p * 16 * PAD * 2 + k2);
            }
#pragma unroll
            for (int mt = 0; mt < 2; mt++)
#pragma unroll
                for (int nt = 0; nt < 8; nt++) {
                    int p = nt >> 1, q = nt & 1;
                    mma_bf16(acc[mt][nt], ah[mt], bh[p][q], bh[p][q + 2]);
                    mma_bf16(acc[mt][nt], al[mt], bh[p][q], bh[p][q + 2]);
                    mma_bf16(acc[mt][nt], ah[mt], bl[p][q], bl[p][q + 2]);
                }
        }

        // ---- epilogue: BN + ReLU in regs, direct store ----
#pragma unroll
        for (int mt = 0; mt < 2; mt++) {
            int r0 = base + wm * 32 + mt * 16 + (lane >> 2);
#pragma unroll
            for (int nt = 0; nt < 8; nt++) {
                int col = wn * 64 + nt * 8 + (lane & 3) * 2;
                float S0 = Sarr[col], S1 = Sarr[col + 1];
                float T0 = Tarr[col], T1 = Tarr[col + 1];
                if (r0 < N_NODES) {
                    float2 v;
                    v.x = fmaxf(acc[mt][nt][0] * S0 + T0, 0.0f);
                    v.y = fmaxf(acc[mt][nt][1] * S1 + T1, 0.0f);
                    *reinterpret_cast<float2*>(out + (size_t)r0 * 128 + col) = v;
                }
                if (r0 + 8 < N_NODES) {
                    float2 v;
                    v.x = fmaxf(acc[mt][nt][2] * S0 + T0, 0.0f);
                    v.y = fmaxf(acc[mt][nt][3] * S1 + T1, 0.0f);
                    *reinterpret_cast<float2*>(out + (size_t)(r0 + 8) * 128 + col) = v;
                }
            }
        }
    }
}

// ---------------- pooling ----------------
__global__ void k_zero_pool() {
    int i = blockIdx.x * blockDim.x + threadIdx.x;
    if (i < N_GRAPH * DIM) g_pool[i] = 0.0f;
    if (i < N_GRAPH) g_gcnt[i] = 0.0f;
}
__global__ void k_pool(const int* __restrict__ batch) {
    int gw = (blockIdx.x * blockDim.x + threadIdx.x) >> 5;
    int lane = threadIdx.x & 31;
    if (gw >= N_NODES) return;
    int c = batch[gw];
    float4 v = reinterpret_cast<const float4*>(g_x)[gw * 32 + lane];
    atomicAdd(reinterpret_cast<float4*>(g_pool) + c * 32 + lane, v);
    if (lane == 0) atomicAdd(&g_gcnt[c], 1.0f);
}

// ---------------- head ----------------
__global__ void k_head(const float* __restrict__ W1, const float* __restrict__ b1,
                       const float* __restrict__ W2, const float* __restrict__ b2,
                       float* __restrict__ out)
{
    __shared__ float sg[DIM];
    __shared__ float sh[DIM];
    int c = blockIdx.x;
    int t = threadIdx.x;
    float cnt = fmaxf(g_gcnt[c], 1.0f);
    sg[t] = g_pool[c * DIM + t] / cnt;
    __syncthreads();
    float acc = b1[t];
#pragma unroll 8
    for (int k = 0; k < DIM; k++) acc += sg[k] * W1[k * DIM + t];
    sh[t] = fmaxf(acc, 0.0f);
    __syncthreads();
    if (t < NCLASS) {
        float o2 = b2[t];
#pragma unroll 8
        for (int k = 0; k < DIM; k++) o2 += sh[k] * W2[k * NCLASS + t];
        out[c * NCLASS + t] = o2;
    }
}

// ---------------- launch ----------------
extern "C" void kernel_launch(void* const* d_in, const int* in_sizes, int n_in,
                              void* d_out, int out_size)
{
    const float* edge_attr = (const float*)d_in[0];
    const int*   edge_index= (const int*)  d_in[1];
    const int*   batch     = (const int*)  d_in[2];
    const float* node_emb  = (const float*)d_in[3];
    const float* edge_W    = (const float*)d_in[4];
    const float* edge_b    = (const float*)d_in[5];
    const float* mlp_W1    = (const float*)d_in[6];
    const float* mlp_b1    = (const float*)d_in[7];
    const float* bn1_g     = (const float*)d_in[8];
    const float* bn1_b     = (const float*)d_in[9];
    const float* bn1_m     = (const float*)d_in[10];
    const float* bn1_v     = (const float*)d_in[11];
    const float* mlp_W2    = (const float*)d_in[12];
    const float* mlp_b2    = (const float*)d_in[13];
    const float* bn2_g     = (const float*)d_in[14];
    const float* bn2_b     = (const float*)d_in[15];
    const float* bn2_m     = (const float*)d_in[16];
    const float* bn2_v     = (const float*)d_in[17];
    const float* head_W1   = (const float*)d_in[18];
    const float* head_b1   = (const float*)d_in[19];
    const float* head_W2   = (const float*)d_in[20];
    const float* head_b2   = (const float*)d_in[21];
    float* out = (float*)d_out;

    cudaFuncSetAttribute(k_mlp_mma, cudaFuncAttributeMaxDynamicSharedMemorySize, MLP_SMEM);

    float *px, *pagg, *pt1;
    __nv_bfloat16 *pwh, *pwl;
    cudaGetSymbolAddress((void**)&px,   g_x);
    cudaGetSymbolAddress((void**)&pagg, g_agg);
    cudaGetSymbolAddress((void**)&pt1,  g_t1);
    cudaGetSymbolAddress((void**)&pwh,  g_Wh);
    cudaGetSymbolAddress((void**)&pwl,  g_Wl);

    // init + weight prep + CSR build (deterministic each replay)
    k_init_x<<<(N_NODES * DIM + 255) / 256, 256>>>(node_emb);
    k_prep_w<<<(10 * 16384 + 255) / 256, 256>>>(mlp_W1, mlp_W2);
    k_zero_deg<<<SCAN_BLOCKS, 256>>>();
    k_hist<<<(N_EDGES + 255) / 256, 256>>>(edge_index);
    k_blocksum<<<SCAN_BLOCKS, 256>>>();
    k_scan_bsum<<<1, 256>>>();
    k_scan_final<<<SCAN_BLOCKS, 256>>>();
    k_scatter<<<(N_EDGES + 255) / 256, 256>>>(edge_index, edge_attr);

    const int TC_GRID = 148;
    for (int l = 0; l < LAYERS; l++) {
        k_edge_csr<<<(N_NODES + 7) / 8, 256>>>(edge_W + l * EDIM * DIM, edge_b + l * DIM);
        int m1 = l * 2, m2 = l * 2 + 1;
        k_mlp_mma<<<TC_GRID, 256, MLP_SMEM>>>(
            pagg, pt1, pwh + m1 * 16384, pwl + m1 * 16384,
            mlp_b1 + l * DIM,
            bn1_g + l * DIM, bn1_b + l * DIM, bn1_m + l * DIM, bn1_v + l * DIM);
        k_mlp_mma<<<TC_GRID, 256, MLP_SMEM>>>(
            pt1, px, pwh + m2 * 16384, pwl + m2 * 16384,
            mlp_b2 + l * DIM,
            bn2_g + l * DIM, bn2_b + l * DIM, bn2_m + l * DIM, bn2_v + l * DIM);
    }

    k_zero_pool<<<(N_GRAPH * DIM + 255) / 256, 256>>>();
    k_pool<<<(N_NODES * 32 + 255) / 256, 256>>>(batch);
    k_head<<<N_GRAPH, DIM>>>(head_W1, head_b1, head_W2, head_b2, out);
}

// round 9
// speedup vs baseline: 2.8369x; 1.3099x over previous
#include <cuda_runtime.h>
#include <cuda_bf16.h>
#include <cstdint>

#define N_NODES 50000
#define N_EDGES 800000
#define N_GRAPH 500
#define DIM     128
#define EDIM    7
#define LAYERS  5
#define NCLASS  10
#define BN_EPS  1e-5f

// ---------------- scratch ----------------
__device__ float g_x  [N_NODES * DIM];
__device__ float g_agg[N_NODES * DIM];
__device__ float g_pool[N_GRAPH * DIM];
__device__ float g_gcnt[N_GRAPH];

// CSR scratch
__device__ int   g_deg [N_NODES];
__device__ int   g_off [N_NODES + 1];
__device__ int   g_bsum[256];
__device__ int   g_fill[N_NODES];
__device__ int   g_esrc[N_EDGES];
__device__ float g_eattr[(size_t)N_EDGES * 8];   // attr in CSR order (padded to 8)

// transposed + bf16-split weight images, row-major [o][k] (10 mats: l*2 + {W1,W2})
__device__ __nv_bfloat16 g_Wh[10 * 16384];
__device__ __nv_bfloat16 g_Wl[10 * 16384];

// ================= helpers =================
__device__ __forceinline__ uint32_t smem_u32(const void* p) {
    uint32_t a;
    asm("{ .reg .u64 t; cvta.to.shared.u64 t, %1; cvt.u32.u64 %0, t; }" : "=r"(a) : "l"(p));
    return a;
}
__device__ __forceinline__ void ldm4(uint32_t* r, uint32_t addr) {
    asm volatile("ldmatrix.sync.aligned.m8n8.x4.shared.b16 {%0,%1,%2,%3}, [%4];"
                 : "=r"(r[0]), "=r"(r[1]), "=r"(r[2]), "=r"(r[3]) : "r"(addr));
}
__device__ __forceinline__ void mma_bf16(float* c, const uint32_t* a, uint32_t b0, uint32_t b1) {
    asm volatile("mma.sync.aligned.m16n8k16.row.col.f32.bf16.bf16.f32 "
                 "{%0,%1,%2,%3}, {%4,%5,%6,%7}, {%8,%9}, {%0,%1,%2,%3};"
                 : "+f"(c[0]), "+f"(c[1]), "+f"(c[2]), "+f"(c[3])
                 : "r"(a[0]), "r"(a[1]), "r"(a[2]), "r"(a[3]), "r"(b0), "r"(b1));
}

// ---------------- weight prep: transpose + bf16 hi/lo split ----------------
__global__ void k_prep_w(const float* __restrict__ W1, const float* __restrict__ W2) {
    int idx = blockIdx.x * blockDim.x + threadIdx.x;
    if (idx >= 10 * 16384) return;
    int mat = idx >> 14;
    int r = idx & 16383;
    int o = r >> 7, k = r & 127;
    int l = mat >> 1;
    const float* W = (mat & 1) ? (W2 + l * 16384) : (W1 + l * 16384);
    float x = W[k * 128 + o];
    __nv_bfloat16 h = __float2bfloat16(x);
    __nv_bfloat16 lo = __float2bfloat16(x - __bfloat162float(h));
    g_Wh[mat * 16384 + o * 128 + k] = h;
    g_Wl[mat * 16384 + o * 128 + k] = lo;
}

// ---------------- CSR build ----------------
__global__ void k_zero_deg() {
    int i = blockIdx.x * blockDim.x + threadIdx.x;
    if (i < N_NODES) g_deg[i] = 0;
}
__global__ void k_hist(const int* __restrict__ ei) {
    int e = blockIdx.x * blockDim.x + threadIdx.x;
    if (e < N_EDGES) atomicAdd(&g_deg[ei[N_EDGES + e]], 1);
}
#define SCAN_BLOCKS ((N_NODES + 255) / 256)   // 196
__global__ void k_blocksum() {
    __shared__ int s[256];
    int i = blockIdx.x * 256 + threadIdx.x;
    s[threadIdx.x] = (i < N_NODES) ? g_deg[i] : 0;
    __syncthreads();
    for (int d = 128; d > 0; d >>= 1) {
        if (threadIdx.x < d) s[threadIdx.x] += s[threadIdx.x + d];
        __syncthreads();
    }
    if (threadIdx.x == 0) g_bsum[blockIdx.x] = s[0];
}
__global__ void k_scan_bsum() {
    __shared__ int s[256];
    int v = (threadIdx.x < SCAN_BLOCKS) ? g_bsum[threadIdx.x] : 0;
    s[threadIdx.x] = v;
    __syncthreads();
    for (int d = 1; d < 256; d <<= 1) {
        int t = (threadIdx.x >= d) ? s[threadIdx.x - d] : 0;
        __syncthreads();
        s[threadIdx.x] += t;
        __syncthreads();
    }
    if (threadIdx.x < SCAN_BLOCKS) g_bsum[threadIdx.x] = s[threadIdx.x] - v;
}
__global__ void k_scan_final() {
    __shared__ int s[256];
    int i = blockIdx.x * 256 + threadIdx.x;
    int v = (i < N_NODES) ? g_deg[i] : 0;
    s[threadIdx.x] = v;
    __syncthreads();
    for (int d = 1; d < 256; d <<= 1) {
        int t = (threadIdx.x >= d) ? s[threadIdx.x - d] : 0;
        __syncthreads();
        s[threadIdx.x] += t;
        __syncthreads();
    }
    int excl = s[threadIdx.x] - v + g_bsum[blockIdx.x];
    if (i < N_NODES) { g_off[i] = excl; g_fill[i] = excl; }
    if (i == N_NODES - 1) g_off[N_NODES] = excl + v;
}
__global__ void k_scatter(const int* __restrict__ ei, const float* __restrict__ attr) {
    int e = blockIdx.x * blockDim.x + threadIdx.x;
    if (e < N_EDGES) {
        int dst = ei[N_EDGES + e];
        int p = atomicAdd(&g_fill[dst], 1);
        g_esrc[p] = ei[e];
        float* d = g_eattr + (size_t)p * 8;
#pragma unroll
        for (int i = 0; i < 7; i++) d[i] = attr[e * 7 + i];
    }
}

// ---------------- edge aggregation, 4-way pipelined (layers 1..4) ----------------
__global__ void __launch_bounds__(256) k_edge_csr(
    const float* __restrict__ eW, const float* __restrict__ eb)
{
    __shared__ float4 sW[EDIM * 32];
    __shared__ float4 sB[32];
    int tid = threadIdx.x;
    if (tid < EDIM * 32) sW[tid] = reinterpret_cast<const float4*>(eW)[tid];
    if (tid < 32)        sB[tid] = reinterpret_cast<const float4*>(eb)[tid];
    __syncthreads();

    int warp = tid >> 5, lane = tid & 31;
    int dst = blockIdx.x * 8 + warp;
    if (dst >= N_NODES) return;

    const float4* X4 = reinterpret_cast<const float4*>(g_x);
    float4 acc = X4[(size_t)dst * 32 + lane];
    float4 b = sB[lane];
    int j = g_off[dst], end = g_off[dst + 1];

    for (; j + 4 <= end; j += 4) {
        float av = g_eattr[(size_t)j * 8 + lane];   // 4 edges x 8 attrs, coalesced
        int s0 = g_esrc[j + 0], s1 = g_esrc[j + 1];
        int s2 = g_esrc[j + 2], s3 = g_esrc[j + 3];
        float4 x0 = X4[(size_t)s0 * 32 + lane];
        float4 x1 = X4[(size_t)s1 * 32 + lane];
        float4 x2 = X4[(size_t)s2 * 32 + lane];
        float4 x3 = X4[(size_t)s3 * 32 + lane];
        float4 e0 = b, e1 = b, e2 = b, e3 = b;
#pragma unroll
        for (int q = 0; q < EDIM; q++) {
            float4 w = sW[q * 32 + lane];
            float a0 = __shfl_sync(0xffffffffu, av, q);
            float a1 = __shfl_sync(0xffffffffu, av, 8 + q);
            float a2 = __shfl_sync(0xffffffffu, av, 16 + q);
            float a3 = __shfl_sync(0xffffffffu, av, 24 + q);
            e0.x += a0 * w.x; e0.y += a0 * w.y; e0.z += a0 * w.z; e0.w += a0 * w.w;
            e1.x += a1 * w.x; e1.y += a1 * w.y; e1.z += a1 * w.z; e1.w += a1 * w.w;
            e2.x += a2 * w.x; e2.y += a2 * w.y; e2.z += a2 * w.z; e2.w += a2 * w.w;
            e3.x += a3 * w.x; e3.y += a3 * w.y; e3.z += a3 * w.z; e3.w += a3 * w.w;
        }
        acc.x += fmaxf(x0.x + e0.x, 0.f) + fmaxf(x1.x + e1.x, 0.f)
               + fmaxf(x2.x + e2.x, 0.f) + fmaxf(x3.x + e3.x, 0.f);
        acc.y += fmaxf(x0.y + e0.y, 0.f) + fmaxf(x1.y + e1.y, 0.f)
               + fmaxf(x2.y + e2.y, 0.f) + fmaxf(x3.y + e3.y, 0.f);
        acc.z += fmaxf(x0.z + e0.z, 0.f) + fmaxf(x1.z + e1.z, 0.f)
               + fmaxf(x2.z + e2.z, 0.f) + fmaxf(x3.z + e3.z, 0.f);
        acc.w += fmaxf(x0.w + e0.w, 0.f) + fmaxf(x1.w + e1.w, 0.f)
               + fmaxf(x2.w + e2.w, 0.f) + fmaxf(x3.w + e3.w, 0.f);
    }
    for (; j < end; j++) {
        int src = g_esrc[j];
        float v = (lane < EDIM) ? g_eattr[(size_t)j * 8 + lane] : 0.0f;
        float4 e = b;
#pragma unroll
        for (int q = 0; q < EDIM; q++) {
            float a = __shfl_sync(0xffffffffu, v, q);
            float4 w = sW[q * 32 + lane];
            e.x += a * w.x; e.y += a * w.y; e.z += a * w.z; e.w += a * w.w;
        }
        float4 xv = X4[(size_t)src * 32 + lane];
        acc.x += fmaxf(xv.x + e.x, 0.0f);
        acc.y += fmaxf(xv.y + e.y, 0.0f);
        acc.z += fmaxf(xv.z + e.z, 0.0f);
        acc.w += fmaxf(xv.w + e.w, 0.0f);
    }
    reinterpret_cast<float4*>(g_agg)[(size_t)dst * 32 + lane] = acc;
}

// ---------------- layer-0 edge: x[src] == node_emb for all nodes (no gather) ----------------
__global__ void __launch_bounds__(256) k_edge_l0(
    const float* __restrict__ node_emb,
    const float* __restrict__ eW, const float* __restrict__ eb)
{
    __shared__ float4 sW[EDIM * 32];
    __shared__ float4 sB[32];
    __shared__ float4 sE[32];
    int tid = threadIdx.x;
    if (tid < EDIM * 32) sW[tid] = reinterpret_cast<const float4*>(eW)[tid];
    if (tid < 32)        sB[tid] = reinterpret_cast<const float4*>(eb)[tid];
    if (tid >= 32 && tid < 64)
        sE[tid - 32] = reinterpret_cast<const float4*>(node_emb)[tid - 32];
    __syncthreads();

    int warp = tid >> 5, lane = tid & 31;
    int dst = blockIdx.x * 8 + warp;
    if (dst >= N_NODES) return;

    float4 em = sE[lane];
    float4 acc = em;                       // seed h = x + agg, x = emb
    float4 b = sB[lane];
    b.x += em.x; b.y += em.y; b.z += em.z; b.w += em.w;   // fold emb into bias
    int j = g_off[dst], end = g_off[dst + 1];

    for (; j + 4 <= end; j += 4) {
        float av = g_eattr[(size_t)j * 8 + lane];
        float4 e0 = b, e1 = b, e2 = b, e3 = b;
#pragma unroll
        for (int q = 0; q < EDIM; q++) {
            float4 w = sW[q * 32 + lane];
            float a0 = __shfl_sync(0xffffffffu, av, q);
            float a1 = __shfl_sync(0xffffffffu, av, 8 + q);
            float a2 = __shfl_sync(0xffffffffu, av, 16 + q);
            float a3 = __shfl_sync(0xffffffffu, av, 24 + q);
            e0.x += a0 * w.x; e0.y += a0 * w.y; e0.z += a0 * w.z; e0.w += a0 * w.w;
            e1.x += a1 * w.x; e1.y += a1 * w.y; e1.z += a1 * w.z; e1.w += a1 * w.w;
            e2.x += a2 * w.x; e2.y += a2 * w.y; e2.z += a2 * w.z; e2.w += a2 * w.w;
            e3.x += a3 * w.x; e3.y += a3 * w.y; e3.z += a3 * w.z; e3.w += a3 * w.w;
        }
        acc.x += fmaxf(e0.x, 0.f) + fmaxf(e1.x, 0.f) + fmaxf(e2.x, 0.f) + fmaxf(e3.x, 0.f);
        acc.y += fmaxf(e0.y, 0.f) + fmaxf(e1.y, 0.f) + fmaxf(e2.y, 0.f) + fmaxf(e3.y, 0.f);
        acc.z += fmaxf(e0.z, 0.f) + fmaxf(e1.z, 0.f) + fmaxf(e2.z, 0.f) + fmaxf(e3.z, 0.f);
        acc.w += fmaxf(e0.w, 0.f) + fmaxf(e1.w, 0.f) + fmaxf(e2.w, 0.f) + fmaxf(e3.w, 0.f);
    }
    for (; j < end; j++) {
        float v = (lane < EDIM) ? g_eattr[(size_t)j * 8 + lane] : 0.0f;
        float4 e = b;
#pragma unroll
        for (int q = 0; q < EDIM; q++) {
            float a = __shfl_sync(0xffffffffu, v, q);
            float4 w = sW[q * 32 + lane];
            e.x += a * w.x; e.y += a * w.y; e.z += a * w.z; e.w += a * w.w;
        }
        acc.x += fmaxf(e.x, 0.0f);
        acc.y += fmaxf(e.y, 0.0f);
        acc.z += fmaxf(e.z, 0.0f);
        acc.w += fmaxf(e.w, 0.0f);
    }
    reinterpret_cast<float4*>(g_agg)[(size_t)dst * 32 + lane] = acc;
}

// ---------------- fused per-layer MLP: GEMM1+BN1+ReLU -> smem -> GEMM2+BN2+ReLU ----------------
#define PAD 136
#define WIMG (128 * PAD)                         // bf16 elems per image
#define FUSED_SMEM (6 * WIMG * 2 + 2048)         // 210,944 B

__device__ __forceinline__ void gemm_128(float (&acc)[2][8][4],
    uint32_t adrAh, uint32_t adrAl, uint32_t adrBh, uint32_t adrBl)
{
#pragma unroll
    for (int mt = 0; mt < 2; mt++)
#pragma unroll
        for (int nt = 0; nt < 8; nt++)
#pragma unroll
            for (int q = 0; q < 4; q++) acc[mt][nt][q] = 0.0f;

#pragma unroll
    for (int ks = 0; ks < 8; ks++) {
        uint32_t k2 = ks * 32;
        uint32_t ah[2][4], al[2][4], bh[4][4], bl[4][4];
        ldm4(ah[0], adrAh + k2);
        ldm4(ah[1], adrAh + 16 * PAD * 2 + k2);
        ldm4(al[0], adrAl + k2);
        ldm4(al[1], adrAl + 16 * PAD * 2 + k2);
#pragma unroll
        for (int p = 0; p < 4; p++) {
            ldm4(bh[p], adrBh + p * 16 * PAD * 2 + k2);
            ldm4(bl[p], adrBl + p * 16 * PAD * 2 + k2);
        }
#pragma unroll
        for (int mt = 0; mt < 2; mt++)
#pragma unroll
            for (int nt = 0; nt < 8; nt++) {
                int p = nt >> 1, q = nt & 1;
                mma_bf16(acc[mt][nt], ah[mt], bh[p][q], bh[p][q + 2]);
                mma_bf16(acc[mt][nt], al[mt], bh[p][q], bh[p][q + 2]);
                mma_bf16(acc[mt][nt], ah[mt], bl[p][q], bl[p][q + 2]);
            }
    }
}

__global__ void __launch_bounds__(256, 1) k_mlp_fused(
    const float* __restrict__ in, float* __restrict__ out,
    const __nv_bfloat16* __restrict__ W1h, const __nv_bfloat16* __restrict__ W1l,
    const __nv_bfloat16* __restrict__ W2h, const __nv_bfloat16* __restrict__ W2l,
    const float* __restrict__ b1,
    const float* __restrict__ g1, const float* __restrict__ bb1,
    const float* __restrict__ m1, const float* __restrict__ v1,
    const float* __restrict__ b2,
    const float* __restrict__ g2, const float* __restrict__ bb2,
    const float* __restrict__ m2, const float* __restrict__ v2)
{
    extern __shared__ char sm[];
    __nv_bfloat16* sW1h = reinterpret_cast<__nv_bfloat16*>(sm);
    __nv_bfloat16* sW1l = sW1h + WIMG;
    __nv_bfloat16* sW2h = sW1l + WIMG;
    __nv_bfloat16* sW2l = sW2h + WIMG;
    __nv_bfloat16* sAh  = sW2l + WIMG;
    __nv_bfloat16* sAl  = sAh + WIMG;
    float* S1 = reinterpret_cast<float*>(sAl + WIMG);
    float* T1 = S1 + 128;
    float* S2 = T1 + 128;
    float* T2 = S2 + 128;

    int tid = threadIdx.x, wid = tid >> 5, lane = tid & 31;

    for (int i = tid; i < 2048; i += 256) {
        int o = i >> 4, kc = (i & 15) * 8;
        *reinterpret_cast<uint4*>(sW1h + o * PAD + kc) = reinterpret_cast<const uint4*>(W1h)[i];
        *reinterpret_cast<uint4*>(sW1l + o * PAD + kc) = reinterpret_cast<const uint4*>(W1l)[i];
        *reinterpret_cast<uint4*>(sW2h + o * PAD + kc) = reinterpret_cast<const uint4*>(W2h)[i];
        *reinterpret_cast<uint4*>(sW2l + o * PAD + kc) = reinterpret_cast<const uint4*>(W2l)[i];
    }
    if (tid < 128) {
        float s1 = g1[tid] * rsqrtf(v1[tid] + BN_EPS);
        S1[tid] = s1;
        T1[tid] = (b1[tid] - m1[tid]) * s1 + bb1[tid];
        float s2 = g2[tid] * rsqrtf(v2[tid] + BN_EPS);
        S2[tid] = s2;
        T2[tid] = (b2[tid] - m2[tid]) * s2 + bb2[tid];
    }

    int wm = wid & 3, wn = wid >> 2;
    uint32_t aOff = ((uint32_t)(wm * 32 + (lane & 15)) * PAD + (lane >> 4) * 8) * 2;
    uint32_t bOff = ((uint32_t)(wn * 64 + (lane & 7) + ((lane >> 3) & 1) * 8) * PAD + (lane >> 4) * 8) * 2;
    uint32_t adrAh  = smem_u32(sAh)  + aOff;
    uint32_t adrAl  = smem_u32(sAl)  + aOff;
    uint32_t adrB1h = smem_u32(sW1h) + bOff;
    uint32_t adrB1l = smem_u32(sW1l) + bOff;
    uint32_t adrB2h = smem_u32(sW2h) + bOff;
    uint32_t adrB2l = smem_u32(sW2l) + bOff;

    const int NTILES = (N_NODES + 127) / 128;   // 391
    const float4* in4 = reinterpret_cast<const float4*>(in);

    for (int t = blockIdx.x; t < NTILES; t += gridDim.x) {
        int base = t * 128;
        __syncthreads();   // everyone done with previous tile's sA

        // ---- A: coalesced load + bf16 hi/lo split ----
        for (int i = tid; i < 4096; i += 256) {
            int row = i >> 5, col = (i & 31) * 4;
            int gr = base + row;
            float4 v = (gr < N_NODES) ? in4[(size_t)gr * 32 + (i & 31)]
                                      : make_float4(0.f, 0.f, 0.f, 0.f);
            __nv_bfloat162 h0 = __float22bfloat162_rn(make_float2(v.x, v.y));
            __nv_bfloat162 h1 = __float22bfloat162_rn(make_float2(v.z, v.w));
            float2 f0 = __bfloat1622float2(h0);
            float2 f1 = __bfloat1622float2(h1);
            __nv_bfloat162 l0 = __float22bfloat162_rn(make_float2(v.x - f0.x, v.y - f0.y));
            __nv_bfloat162 l1 = __float22bfloat162_rn(make_float2(v.z - f1.x, v.w - f1.y));
            uint2 hp = make_uint2(*reinterpret_cast<uint32_t*>(&h0), *reinterpret_cast<uint32_t*>(&h1));
            uint2 lp = make_uint2(*reinterpret_cast<uint32_t*>(&l0), *reinterpret_cast<uint32_t*>(&l1));
            *reinterpret_cast<uint2*>(sAh + row * PAD + col) = hp;
            *reinterpret_cast<uint2*>(sAl + row * PAD + col) = lp;
        }
        __syncthreads();

        // ---- GEMM1 ----
        float acc[2][8][4];
        gemm_128(acc, adrAh, adrAl, adrB1h, adrB1l);
        __syncthreads();   // all warps done reading sA

        // ---- epilogue1: BN1 + ReLU -> bf16 split back into sA ----
#pragma unroll
        for (int mt = 0; mt < 2; mt++) {
            int r0 = wm * 32 + mt * 16 + (lane >> 2);
#pragma unroll
            for (int nt = 0; nt < 8; nt++) {
                int col = wn * 64 + nt * 8 + (lane & 3) * 2;
                float Sa = S1[col], Sb2 = S1[col + 1];
                float Ta = T1[col], Tb = T1[col + 1];
                float y0 = fmaxf(acc[mt][nt][0] * Sa + Ta, 0.0f);
                float y1 = fmaxf(acc[mt][nt][1] * Sb2 + Tb, 0.0f);
                float y2 = fmaxf(acc[mt][nt][2] * Sa + Ta, 0.0f);
                float y3 = fmaxf(acc[mt][nt][3] * Sb2 + Tb, 0.0f);
                __nv_bfloat162 h0 = __float22bfloat162_rn(make_float2(y0, y1));
                __nv_bfloat162 h1 = __float22bfloat162_rn(make_float2(y2, y3));
                float2 f0 = __bfloat1622float2(h0);
                float2 f1 = __bfloat1622float2(h1);
                __nv_bfloat162 l0 = __float22bfloat162_rn(make_float2(y0 - f0.x, y1 - f0.y));
                __nv_bfloat162 l1 = __float22bfloat162_rn(make_float2(y2 - f1.x, y3 - f1.y));
                *reinterpret_cast<uint32_t*>(sAh + r0 * PAD + col) = *reinterpret_cast<uint32_t*>(&h0);
                *reinterpret_cast<uint32_t*>(sAl + r0 * PAD + col) = *reinterpret_cast<uint32_t*>(&l0);
                *reinterpret_cast<uint32_t*>(sAh + (r0 + 8) * PAD + col) = *reinterpret_cast<uint32_t*>(&h1);
                *reinterpret_cast<uint32_t*>(sAl + (r0 + 8) * PAD + col) = *reinterpret_cast<uint32_t*>(&l1);
            }
        }
        __syncthreads();

        // ---- GEMM2 ----
        gemm_128(acc, adrAh, adrAl, adrB2h, adrB2l);

        // ---- epilogue2: BN2 + ReLU -> global ----
#pragma unroll
        for (int mt = 0; mt < 2; mt++) {
            int r0 = base + wm * 32 + mt * 16 + (lane >> 2);
#pragma unroll
            for (int nt = 0; nt < 8; nt++) {
                int col = wn * 64 + nt * 8 + (lane & 3) * 2;
                float Sa = S2[col], Sb2 = S2[col + 1];
                float Ta = T2[col], Tb = T2[col + 1];
                if (r0 < N_NODES) {
                    float2 v;
                    v.x = fmaxf(acc[mt][nt][0] * Sa + Ta, 0.0f);
                    v.y = fmaxf(acc[mt][nt][1] * Sb2 + Tb, 0.0f);
                    *reinterpret_cast<float2*>(out + (size_t)r0 * 128 + col) = v;
                }
                if (r0 + 8 < N_NODES) {
                    float2 v;
                    v.x = fmaxf(acc[mt][nt][2] * Sa + Ta, 0.0f);
                    v.y = fmaxf(acc[mt][nt][3] * Sb2 + Tb, 0.0f);
                    *reinterpret_cast<float2*>(out + (size_t)(r0 + 8) * 128 + col) = v;
                }
            }
        }
    }
}

// ---------------- pooling ----------------
__global__ void k_zero_pool() {
    int i = blockIdx.x * blockDim.x + threadIdx.x;
    if (i < N_GRAPH * DIM) g_pool[i] = 0.0f;
    if (i < N_GRAPH) g_gcnt[i] = 0.0f;
}
__global__ void k_pool(const int* __restrict__ batch) {
    int gw = (blockIdx.x * blockDim.x + threadIdx.x) >> 5;
    int lane = threadIdx.x & 31;
    if (gw >= N_NODES) return;
    int c = batch[gw];
    float4 v = reinterpret_cast<const float4*>(g_x)[(size_t)gw * 32 + lane];
    atomicAdd(reinterpret_cast<float4*>(g_pool) + c * 32 + lane, v);
    if (lane == 0) atomicAdd(&g_gcnt[c], 1.0f);
}

// ---------------- head ----------------
__global__ void k_head(const float* __restrict__ W1, const float* __restrict__ b1,
                       const float* __restrict__ W2, const float* __restrict__ b2,
                       float* __restrict__ out)
{
    __shared__ float sg[DIM];
    __shared__ float sh[DIM];
    int c = blockIdx.x;
    int t = threadIdx.x;
    float cnt = fmaxf(g_gcnt[c], 1.0f);
    sg[t] = g_pool[c * DIM + t] / cnt;
    __syncthreads();
    float acc = b1[t];
#pragma unroll 8
    for (int k = 0; k < DIM; k++) acc += sg[k] * W1[k * DIM + t];
    sh[t] = fmaxf(acc, 0.0f);
    __syncthreads();
    if (t < NCLASS) {
        float o2 = b2[t];
#pragma unroll 8
        for (int k = 0; k < DIM; k++) o2 += sh[k] * W2[k * NCLASS + t];
        out[c * NCLASS + t] = o2;
    }
}

// ---------------- launch ----------------
extern "C" void kernel_launch(void* const* d_in, const int* in_sizes, int n_in,
                              void* d_out, int out_size)
{
    const float* edge_attr = (const float*)d_in[0];
    const int*   edge_index= (const int*)  d_in[1];
    const int*   batch     = (const int*)  d_in[2];
    const float* node_emb  = (const float*)d_in[3];
    const float* edge_W    = (const float*)d_in[4];
    const float* edge_b    = (const float*)d_in[5];
    const float* mlp_W1    = (const float*)d_in[6];
    const float* mlp_b1    = (const float*)d_in[7];
    const float* bn1_g     = (const float*)d_in[8];
    const float* bn1_b     = (const float*)d_in[9];
    const float* bn1_m     = (const float*)d_in[10];
    const float* bn1_v     = (const float*)d_in[11];
    const float* mlp_W2    = (const float*)d_in[12];
    const float* mlp_b2    = (const float*)d_in[13];
    const float* bn2_g     = (const float*)d_in[14];
    const float* bn2_b     = (const float*)d_in[15];
    const float* bn2_m     = (const float*)d_in[16];
    const float* bn2_v     = (const float*)d_in[17];
    const float* head_W1   = (const float*)d_in[18];
    const float* head_b1   = (const float*)d_in[19];
    const float* head_W2   = (const float*)d_in[20];
    const float* head_b2   = (const float*)d_in[21];
    float* out = (float*)d_out;

    cudaFuncSetAttribute(k_mlp_fused, cudaFuncAttributeMaxDynamicSharedMemorySize, FUSED_SMEM);

    float *px, *pagg;
    __nv_bfloat16 *pwh, *pwl;
    cudaGetSymbolAddress((void**)&px,   g_x);
    cudaGetSymbolAddress((void**)&pagg, g_agg);
    cudaGetSymbolAddress((void**)&pwh,  g_Wh);
    cudaGetSymbolAddress((void**)&pwl,  g_Wl);

    // weight prep + CSR build (deterministic each replay)
    k_prep_w<<<(10 * 16384 + 255) / 256, 256>>>(mlp_W1, mlp_W2);
    k_zero_deg<<<SCAN_BLOCKS, 256>>>();
    k_hist<<<(N_EDGES + 255) / 256, 256>>>(edge_index);
    k_blocksum<<<SCAN_BLOCKS, 256>>>();
    k_scan_bsum<<<1, 256>>>();
    k_scan_final<<<SCAN_BLOCKS, 256>>>();
    k_scatter<<<(N_EDGES + 255) / 256, 256>>>(edge_index, edge_attr);

    const int TC_GRID = 148;
    for (int l = 0; l < LAYERS; l++) {
        if (l == 0)
            k_edge_l0<<<(N_NODES + 7) / 8, 256>>>(node_emb, edge_W, edge_b);
        else
            k_edge_csr<<<(N_NODES + 7) / 8, 256>>>(edge_W + l * EDIM * DIM, edge_b + l * DIM);
        int m1 = l * 2, m2 = l * 2 + 1;
        k_mlp_fused<<<TC_GRID, 256, FUSED_SMEM>>>(
            pagg, px,
            pwh + m1 * 16384, pwl + m1 * 16384,
            pwh + m2 * 16384, pwl + m2 * 16384,
            mlp_b1 + l * DIM, bn1_g + l * DIM, bn1_b + l * DIM, bn1_m + l * DIM, bn1_v + l * DIM,
            mlp_b2 + l * DIM, bn2_g + l * DIM, bn2_b + l * DIM, bn2_m + l * DIM, bn2_v + l * DIM);
    }

    k_zero_pool<<<(N_GRAPH * DIM + 255) / 256, 256>>>();
    k_pool<<<(N_NODES * 32 + 255) / 256, 256>>>(batch);
    k_head<<<N_GRAPH, DIM>>>(head_W1, head_b1, head_W2, head_b2, out);
}